// round 3
// baseline (speedup 1.0000x reference)
#include <cuda_runtime.h>
#include <math.h>

#define COMMIT_SCALE 1.25f   // 1 + COMMITMENT_COST; e_latent == q_latent in forward
#define EPS 1e-6f

#define LUT_SIZE 262144      // taxid range [0, 2E) = [0, 100000)
#define E_MAX    50016
#define N_MAX    524288
#define SENTINEL 0x7FFFFFFF

// Scratch (__device__ globals — no allocation allowed)
__device__ int    g_lut[LUT_SIZE];
__device__ float  g_qcache[E_MAX * 65];   // [E][65] = exact masked output row
__device__ int    g_info[N_MAX];          // idx or -1
__device__ float  g_partial[N_MAX];       // accumulated lorentz inner product (lip)
__device__ double g_loss_sum;
__device__ int    g_valid_cnt;

// ---------------- K1: init scratch + precompute lorentz codebook ----------------
__global__ void __launch_bounds__(256) vq_init_codebook(
    const float* __restrict__ emb, int E, int N)
{
    const int tid = blockIdx.x * blockDim.x + threadIdx.x;
    const int nth = gridDim.x * blockDim.x;
    if (tid == 0) { g_loss_sum = 0.0; g_valid_cnt = 0; }
    for (int i = tid; i < LUT_SIZE; i += nth) g_lut[i] = SENTINEL;
    for (int i = tid; i < N; i += nth)        g_partial[i] = 0.0f;

    const int lane = threadIdx.x & 31;
    const int gw = tid >> 5, nw = nth >> 5;
    for (int e = gw; e < E; e += nw) {
        const float wA = __ldg(&emb[(size_t)e * 64 + lane]);
        const float wB = __ldg(&emb[(size_t)e * 64 + lane + 32]);
        const float xA = 3.0f * tanhf(wA);
        const float xB = 3.0f * tanhf(wB);

        float s = xA * xA + xB * xB;
        #pragma unroll
        for (int off = 16; off; off >>= 1)
            s += __shfl_xor_sync(0xFFFFFFFFu, s, off);

        float n = sqrtf(fmaxf(s, EPS));
        n = fminf(n, 10.0f);
        const float sh = sinhf(n) / n;
        const float ch = coshf(n);

        float* q = g_qcache + (size_t)e * 65;
        if (lane == 0) q[0] = ch;
        q[1 + lane]  = sh * xA;
        q[33 + lane] = sh * xB;
    }
}

// ---------------- K2: scatter key -> LUT ----------------
__global__ void vq_lut_kernel(const int* __restrict__ key, int E) {
    int i = blockIdx.x * blockDim.x + threadIdx.x;
    if (i < E) {
        int v = key[i];
        if (v >= 0 && v < LUT_SIZE) atomicMin(&g_lut[v], i);
    }
}

// ---------------- K3: per-row info (idx or -1) + valid count ----------------
__global__ void __launch_bounds__(256) vq_info_kernel(
    const int* __restrict__ lineages, int N, int E)
{
    int i = blockIdx.x * blockDim.x + threadIdx.x;
    bool m = false;
    if (i < N) {
        const int taxid = __ldg(&lineages[2 * i + 1]);
        int idx = ((unsigned)taxid < (unsigned)LUT_SIZE) ? __ldg(&g_lut[taxid]) : SENTINEL;
        m = (idx < E);
        g_info[i] = m ? idx : -1;
    }
    unsigned b = __ballot_sync(0xFFFFFFFFu, m);
    if ((threadIdx.x & 31) == 0) {
        int c = __popc(b);
        if (c) atomicAdd(&g_valid_cnt, c);
    }
}

// ---------------- K4: flat vectorized main stream ----------------
// Thread k writes d_out[4k..4k+3]; quantized element f = dest - 1.
// d_out[0] (the loss slot) gets garbage here; finalize overwrites it.
__global__ void __launch_bounds__(256) vq_main_kernel(
    const float* __restrict__ inp,   // [Mq] flat inputs_all
    float*       __restrict__ dout,  // d_out (element 0 = loss slot)
    int Mq, int N)
{
    const int k    = blockIdx.x * blockDim.x + threadIdx.x;
    const int lane = threadIdx.x & 31;
    const int e0   = 4 * k;

    float4 v = make_float4(0.f, 0.f, 0.f, 0.f);
    if (e0 + 4 <= Mq) v = *reinterpret_cast<const float4*>(inp + e0);

    float prevw = __shfl_up_sync(0xFFFFFFFFu, v.w, 1);
    if (lane == 0)
        prevw = (e0 >= 1 && e0 - 1 < Mq) ? __ldg(inp + e0 - 1) : 0.0f;

    const int f0 = e0 - 1;
    int row0, col0;
    if (f0 < 0) { row0 = 0; col0 = -1; }
    else { row0 = (int)((unsigned)f0 / 65u); col0 = f0 - row0 * 65; }

    const bool wraps   = (col0 + 3 >= 65);
    const int  info_lo = (row0 < N) ? __ldg(&g_info[row0]) : -1;
    const int  info_hi = (wraps && row0 + 1 < N) ? __ldg(&g_info[row0 + 1]) : -1;

    const float a[4] = {prevw, v.x, v.y, v.z};
    float o[4];
    float s_lo = 0.f, s_hi = 0.f;

    #pragma unroll
    for (int i = 0; i < 4; i++) {
        int col = col0 + i;
        const bool w = (col >= 65);
        const int  inf = w ? info_hi : info_lo;
        if (w) col -= 65;
        const int  f = f0 + i;
        const bool valid = (f >= 0) && (f < Mq);
        const float av = a[i];
        float ov = valid ? av : 0.0f;
        if (valid && inf >= 0) {
            const float q = __ldg(&g_qcache[inf * 65 + col]);
            ov = q;
            const float c = (col == 0) ? (-q * av) : (q * av);  // accumulate lip
            if (w) s_hi += c; else s_lo += c;
        }
        o[i] = ov;
    }

    if (e0 + 3 <= Mq) {
        *reinterpret_cast<float4*>(dout + e0) = make_float4(o[0], o[1], o[2], o[3]);
    } else {
        #pragma unroll
        for (int i = 0; i < 4; i++)
            if (e0 + i >= 1 && e0 + i <= Mq) dout[e0 + i] = o[i];
    }

    // warp-segmented reduction of lip partials: warp spans <= 3 rows
    const unsigned anyb = __ballot_sync(0xFFFFFFFFu, (s_lo != 0.f) || (s_hi != 0.f));
    if (anyb) {
        const int rb = __shfl_sync(0xFFFFFFFFu, row0, 0);
        const int d  = row0 - rb;                       // 0..2 for in-range lanes
        float acc0 = (d == 0) ? s_lo : 0.f;
        float acc1 = (d == 0) ? s_hi : ((d == 1) ? s_lo : 0.f);
        float acc2 = (d == 1) ? s_hi : ((d == 2) ? s_lo : 0.f);
        float acc3 = (d == 2) ? s_hi : 0.f;
        #pragma unroll
        for (int off = 16; off; off >>= 1) {
            acc0 += __shfl_xor_sync(0xFFFFFFFFu, acc0, off);
            acc1 += __shfl_xor_sync(0xFFFFFFFFu, acc1, off);
            acc2 += __shfl_xor_sync(0xFFFFFFFFu, acc2, off);
            acc3 += __shfl_xor_sync(0xFFFFFFFFu, acc3, off);
        }
        if (lane == 0) {
            if (acc0 != 0.f && rb     < N) atomicAdd(&g_partial[rb],     acc0);
            if (acc1 != 0.f && rb + 1 < N) atomicAdd(&g_partial[rb + 1], acc1);
            if (acc2 != 0.f && rb + 2 < N) atomicAdd(&g_partial[rb + 2], acc2);
            if (acc3 != 0.f && rb + 3 < N) atomicAdd(&g_partial[rb + 3], acc3);
        }
    }
}

// ---------------- K5: per-row acosh + reduce ----------------
__global__ void __launch_bounds__(256) vq_loss_kernel(int N) {
    const int i = blockIdx.x * blockDim.x + threadIdx.x;
    const int lane = threadIdx.x & 31;
    const int warp = threadIdx.x >> 5;

    float local = 0.f;
    if (i < N && __ldg(&g_info[i]) >= 0) {
        const float p = g_partial[i];                  // p = lip
        local = acoshf(fmaxf(-p, 1.0f + EPS));
    }
    #pragma unroll
    for (int off = 16; off; off >>= 1)
        local += __shfl_xor_sync(0xFFFFFFFFu, local, off);

    __shared__ float s[8];
    if (lane == 0) s[warp] = local;
    __syncthreads();
    if (threadIdx.x == 0) {
        float bl = 0.f;
        const int nw = blockDim.x >> 5;
        for (int w = 0; w < nw; w++) bl += s[w];
        atomicAdd(&g_loss_sum, (double)bl);
    }
}

// ---------------- K6: finalize ----------------
__global__ void vq_finalize_kernel(float* __restrict__ out0) {
    double nv = (double)g_valid_cnt;
    if (nv < 1.0) nv = 1.0;
    out0[0] = (float)((double)COMMIT_SCALE * g_loss_sum / nv);
}

extern "C" void kernel_launch(void* const* d_in, const int* in_sizes, int n_in,
                              void* d_out, int out_size) {
    const float* inputs   = (const float*)d_in[0];
    const int*   lineages = (const int*)  d_in[1];
    const float* emb      = (const float*)d_in[2];
    const int*   key      = (const int*)  d_in[3];

    int N = in_sizes[1] / 2;
    if (N > N_MAX) N = N_MAX;
    int E = in_sizes[3];
    if (E > E_MAX) E = E_MAX;
    const int Mq = N * 65;

    float* out = (float*)d_out;

    vq_init_codebook<<<6250, 256>>>(emb, E, N);                 // 50000 warps
    vq_lut_kernel<<<(E + 255) / 256, 256>>>(key, E);
    vq_info_kernel<<<(N + 255) / 256, 256>>>(lineages, N, E);

    const int T = (Mq >> 2) + 1;                                // dest elems Mq+1, 4/thread
    vq_main_kernel<<<(T + 255) / 256, 256>>>(inputs, out, Mq, N);

    vq_loss_kernel<<<(N + 255) / 256, 256>>>(N);
    vq_finalize_kernel<<<1, 1>>>(out);
}

// round 4
// speedup vs baseline: 1.0689x; 1.0689x over previous
#include <cuda_runtime.h>
#include <math.h>

#define COMMIT_SCALE 1.25f   // 1 + COMMITMENT_COST; e_latent == q_latent in forward
#define EPS 1e-6f

#define LUT_SIZE 262144      // taxid range [0, 2E) = [0, 100000)
#define E_MAX    50016
#define SENTINEL 0x7FFFFFFF

__device__ int    g_lut[LUT_SIZE];
__device__ float  g_qcache[E_MAX * 65];   // [E][65] = exact masked output row
__device__ double g_loss_sum;
__device__ int    g_valid_cnt;

// ---------------- K1: init LUT + precompute lorentz codebook ----------------
__global__ void __launch_bounds__(256) vq_init_codebook(
    const float* __restrict__ emb, int E)
{
    const int tid = blockIdx.x * blockDim.x + threadIdx.x;
    const int nth = gridDim.x * blockDim.x;
    if (tid == 0) { g_loss_sum = 0.0; g_valid_cnt = 0; }
    for (int i = tid; i < LUT_SIZE; i += nth) g_lut[i] = SENTINEL;

    const int lane = threadIdx.x & 31;
    const int gw = tid >> 5, nw = nth >> 5;
    for (int e = gw; e < E; e += nw) {
        const float wA = __ldg(&emb[(size_t)e * 64 + lane]);
        const float wB = __ldg(&emb[(size_t)e * 64 + lane + 32]);
        const float xA = 3.0f * tanhf(wA);
        const float xB = 3.0f * tanhf(wB);

        float s = xA * xA + xB * xB;
        #pragma unroll
        for (int off = 16; off; off >>= 1)
            s += __shfl_xor_sync(0xFFFFFFFFu, s, off);

        float n = sqrtf(fmaxf(s, EPS));
        n = fminf(n, 10.0f);
        const float sh = sinhf(n) / n;
        const float ch = coshf(n);

        float* q = g_qcache + (size_t)e * 65;
        if (lane == 0) q[0] = ch;
        q[1 + lane]  = sh * xA;
        q[33 + lane] = sh * xB;
    }
}

// ---------------- K2: scatter key -> LUT ----------------
__global__ void vq_lut_kernel(const int* __restrict__ key, int E) {
    int i = blockIdx.x * blockDim.x + threadIdx.x;
    if (i < E) {
        int v = key[i];
        if (v >= 0 && v < LUT_SIZE) atomicMin(&g_lut[v], i);
    }
}

// ---------------- K3: main — warp per row-tile of 32, no blocking reductions ----------------
__global__ void __launch_bounds__(256) vq_main_kernel(
    const float* __restrict__ inputs,    // [N, 65]
    const int*   __restrict__ lineages,  // [N, 2]
    float*       __restrict__ out,       // [N, 65] (d_out + 1)
    int N, int E)
{
    // per-warp dot-partial slab: 32 rows x 32 lanes, 33-stride skew (conflict-free)
    __shared__ float s_part[8][32 * 33];

    const int lane        = threadIdx.x & 31;
    const int warp_in_blk = threadIdx.x >> 5;
    const int gwarp       = (blockIdx.x * blockDim.x + threadIdx.x) >> 5;
    const int nwarps      = (gridDim.x * blockDim.x) >> 5;

    float* sp = s_part[warp_in_blk];

    float loss_local = 0.0f;
    int   cnt_local  = 0;

    for (int base = gwarp * 32; base < N; base += nwarps * 32) {
        // batched LUT probe: lane i resolves row base+i
        const int myrow = base + lane;
        int my_idx = SENTINEL;
        if (myrow < N) {
            const int taxid = __ldg(&lineages[2 * myrow + 1]);
            if ((unsigned)taxid < (unsigned)LUT_SIZE)
                my_idx = __ldg(&g_lut[taxid]);
        }
        const unsigned mbits = __ballot_sync(0xFFFFFFFFu, my_idx < E);
        const int nrows = min(32, N - base);

        // streaming phase: each iteration fully independent (no cross-lane waits)
        for (int j = 0; j < nrows; j++) {
            const int row = base + j;
            const float* a = inputs + (size_t)row * 65;
            float*       o = out    + (size_t)row * 65;

            const float a0 = __ldg(&a[0]);
            const float aA = __ldg(&a[1 + lane]);
            const float aB = __ldg(&a[33 + lane]);

            if ((mbits >> j) & 1u) {
                const int idx = __shfl_sync(0xFFFFFFFFu, my_idx, j);
                const float* q = g_qcache + (size_t)idx * 65;
                const float q0 = __ldg(&q[0]);
                const float qA = __ldg(&q[1 + lane]);
                const float qB = __ldg(&q[33 + lane]);

                float p = qA * aA + qB * aB;          // lip partial
                if (lane == 0) p -= q0 * a0;          // full lip = sum(p) over lanes
                sp[j * 33 + lane] = p;                // fire-and-forget

                if (lane == 0) o[0] = q0;
                o[1 + lane]  = qA;
                o[33 + lane] = qB;
            } else {
                if (lane == 0) o[0] = a0;
                o[1 + lane]  = aA;
                o[33 + lane] = aB;
            }
        }
        __syncwarp();

        // reduction phase: lane l reduces its own row (parallel across 32 rows)
        if (my_idx < E && myrow < N) {
            float s = 0.0f;
            #pragma unroll
            for (int c = 0; c < 32; c++)
                s += sp[lane * 33 + c];               // bank (lane+c)%32: conflict-free
            const float d = acoshf(fmaxf(-s, 1.0f + EPS));
            loss_local += d;
            cnt_local  += 1;
        }
        __syncwarp();                                  // slab reused next tile
    }

    // reduce loss across warp, then block, then one atomic pair
    #pragma unroll
    for (int off = 16; off; off >>= 1) {
        loss_local += __shfl_xor_sync(0xFFFFFFFFu, loss_local, off);
        cnt_local  += __shfl_xor_sync(0xFFFFFFFFu, cnt_local, off);
    }
    __shared__ float s_loss[8];
    __shared__ int   s_cnt[8];
    if (lane == 0) { s_loss[warp_in_blk] = loss_local; s_cnt[warp_in_blk] = cnt_local; }
    __syncthreads();
    if (threadIdx.x == 0) {
        float bl = 0.0f; int bc = 0;
        for (int i = 0; i < 8; i++) { bl += s_loss[i]; bc += s_cnt[i]; }
        atomicAdd(&g_loss_sum, (double)bl);
        atomicAdd(&g_valid_cnt, bc);
    }
}

// ---------------- K4: finalize ----------------
__global__ void vq_finalize_kernel(float* __restrict__ out0) {
    double nv = (double)g_valid_cnt;
    if (nv < 1.0) nv = 1.0;
    out0[0] = (float)((double)COMMIT_SCALE * g_loss_sum / nv);
}

extern "C" void kernel_launch(void* const* d_in, const int* in_sizes, int n_in,
                              void* d_out, int out_size) {
    const float* inputs   = (const float*)d_in[0];
    const int*   lineages = (const int*)  d_in[1];
    const float* emb      = (const float*)d_in[2];
    const int*   key      = (const int*)  d_in[3];

    const int N = in_sizes[1] / 2;
    int E = in_sizes[3];
    if (E > E_MAX) E = E_MAX;

    float* out = (float*)d_out;

    vq_init_codebook<<<6250, 256>>>(emb, E);
    vq_lut_kernel<<<(E + 255) / 256, 256>>>(key, E);
    vq_main_kernel<<<2048, 256>>>(inputs, lineages, out + 1, N, E);
    vq_finalize_kernel<<<1, 1>>>(out);
}